// round 10
// baseline (speedup 1.0000x reference)
#include <cuda_runtime.h>
#include <cstdint>

// Problem dims
#define HWX  16384      // 128*128
#define CHWX 1048576    // 64*128*128
#define TOTX 8388608    // 8*64*128*128

typedef unsigned long long ull;

// ---------------- device scratch (allocation-free rule: device globals) ----
__device__ __align__(16) float g_hs [TOTX];   // south row-scan, natural [b][c][h][w]
__device__ __align__(16) float g_hn [TOTX];   // north row-scan, natural
__device__ __align__(16) float g_hsT[TOTX];   // [b][c][w][h]
__device__ __align__(16) float g_hnT[TOTX];
__device__ __align__(16) float g_yT [TOTX];   // y transposed [b][c][w][h]
__device__ __align__(16) float g_col[4][TOTX];// per-direction col-scan output, [b][c][w][h]

// ---------------- f32x2 helpers -------------------------------------------
__device__ __forceinline__ void fma2(ull& acc, ull a, ull b) {
    asm("fma.rn.f32x2 %0, %1, %2, %0;" : "+l"(acc) : "l"(a), "l"(b));
}
__device__ __forceinline__ float2 unpk(ull v) {
    float2 f; asm("mov.b64 {%0, %1}, %2;" : "=f"(f.x), "=f"(f.y) : "l"(v)); return f;
}
__device__ __forceinline__ ull dal(double d) { return __double_as_longlong(d); }

// ---------------- cp.async helpers ----------------------------------------
__device__ __forceinline__ void cpasync16(void* s, const void* g) {
    uint32_t sa = (uint32_t)__cvta_generic_to_shared(s);
    asm volatile("cp.async.ca.shared.global [%0], [%1], 16;" :: "r"(sa), "l"(g) : "memory");
}
__device__ __forceinline__ void cpcommit() { asm volatile("cp.async.commit_group;" ::: "memory"); }
__device__ __forceinline__ void cpwait0()  { asm volatile("cp.async.wait_group 0;"  ::: "memory"); }

// DSMEM scalar store into peer CTA's shared memory (cluster rank `rank`)
__device__ __forceinline__ void dsmem_store(float* laddr, int rank, float v) {
    uint32_t la = (uint32_t)__cvta_generic_to_shared(laddr);
    uint32_t ra;
    asm volatile("mapa.shared::cluster.u32 %0, %1, %2;" : "=r"(ra) : "r"(la), "r"(rank));
    asm volatile("st.shared::cluster.f32 [%0], %1;" :: "r"(ra), "f"(v) : "memory");
}

__device__ __forceinline__ float4 relu4(float4 v) {
    v.x = fmaxf(v.x, 0.f); v.y = fmaxf(v.y, 0.f);
    v.z = fmaxf(v.z, 0.f); v.w = fmaxf(v.w, 0.f);
    return v;
}

extern __shared__ __align__(16) float smdyn[];

// ===========================================================================
// Kernel 1: row scans (south dir=0, north dir=1).
// grid (8 w-tiles, 8 batch, 2 dirs), 128 threads.
// Thread tile: 4 o x 2 w (one f32x2 pair). Weights PRE-DUPLICATED [c][o*2]:
// LDS.128 -> (w0,w0,w1,w1), zero per-FMA MOVs. x/y double-buffered cp.async.
// smem (floats): WaD 0 (8192), WbD 8192 (8192), sx 16384 (2x1024),
//                sy 18432 (2x1024), sh 20480 (1024), ba 21504, bb 21568
//                -> 21632 fl = 86528 B
// ===========================================================================
__global__ void __launch_bounds__(128, 1) row_scan_kernel(
    const float* __restrict__ x, const float* __restrict__ y,
    const float* __restrict__ Wc, const float* __restrict__ bc)
{
    float* sWaD = smdyn;
    float* sWbD = smdyn + 8192;
    float* sx   = smdyn + 16384;
    float* sy   = smdyn + 18432;
    float* sh   = smdyn + 20480;
    float* sba  = smdyn + 21504;
    float* sbb  = smdyn + 21568;

    const int dir = blockIdx.z;          // 0 = south, 1 = north
    const int b   = blockIdx.y;
    const int w0  = blockIdx.x * 16;
    const int t   = threadIdx.x;

    const int ka = dir ? 8 : 0;
    const float* Wa = Wc + ka * 4096;
    const float* Wb = Wc + (ka + 1) * 4096;
    for (int idx = t; idx < 4096; idx += 128) {
        int o = idx >> 6, c = idx & 63;
        float wa = Wa[idx], wb = Wb[idx];
        sWaD[c * 128 + o * 2] = wa; sWaD[c * 128 + o * 2 + 1] = wa;
        sWbD[c * 128 + o * 2] = wb; sWbD[c * 128 + o * 2 + 1] = wb;
    }
    if (t < 64) { sba[t] = bc[ka * 64 + t]; sbb[t] = bc[(ka + 1) * 64 + t]; }

    const float* xb = x + b * CHWX + w0;
    const float* yb = y + b * CHWX + w0;
    float* hb = (dir ? g_hn : g_hs) + b * CHWX + w0;

    // boundary row init: 8 floats per thread
    {
        const int r0 = dir ? 127 : 0;
        const int c  = t >> 1;
        const int wv = (t & 1) * 8;
        #pragma unroll
        for (int kk = 0; kk < 2; ++kk) {
            float4 v = *(const float4*)(xb + c * HWX + r0 * 128 + wv + kk * 4);
            if (dir) v = relu4(v);
            *(float4*)(sh + c * 16 + wv + kk * 4) = v;
            *(float4*)(hb + c * HWX + r0 * 128 + wv + kk * 4) = v;
        }
    }
    // prefetch step 1 tiles into parity-1 buffers
    {
        const int r2  = dir ? 126 : 1;
        const int yr2 = dir ? 127 : 0;
        #pragma unroll
        for (int k = 0; k < 2; ++k) {
            int q = t + 128 * k;
            int c = q >> 2, w = (q & 3) * 4;
            cpasync16(sx + 1024 + c * 16 + w, xb + c * HWX + r2  * 128 + w);
            cpasync16(sy + 1024 + c * 16 + w, yb + c * HWX + yr2 * 128 + w);
        }
        cpcommit();
    }

    const int o4 = (t >> 3) * 4;         // 4 out-channels
    const int wq = (t & 7) * 2;          // one w pair

    for (int i = 1; i < 128; ++i) {
        const int p = i & 1;
        const float* sxP = sx + p * 1024;
        const float* syP = sy + p * 1024;
        const int r = dir ? 127 - i : i;

        cpwait0();
        __syncthreads();

        if (i < 127) {
            const int r2  = dir ? 127 - (i + 1) : (i + 1);
            const int yr2 = dir ? r2 + 1 : r2 - 1;
            float* sxN = sx + (1 - p) * 1024;
            float* syN = sy + (1 - p) * 1024;
            #pragma unroll
            for (int k = 0; k < 2; ++k) {
                int q = t + 128 * k;
                int c = q >> 2, w = (q & 3) * 4;
                cpasync16(sxN + c * 16 + w, xb + c * HWX + r2  * 128 + w);
                cpasync16(syN + c * 16 + w, yb + c * HWX + yr2 * 128 + w);
            }
            cpcommit();
        }

        ull aa[4], ab[4];
        #pragma unroll
        for (int k = 0; k < 4; ++k) { aa[k] = 0ULL; ab[k] = 0ULL; }

        #pragma unroll 8
        for (int c = 0; c < 64; ++c) {
            ull xv = dal(*(const double*)(sxP + c * 16 + wq));
            ull hv = dal(*(const double*)(sh  + c * 16 + wq));
            double2 wa01 = *(const double2*)(sWaD + c * 128 + o4 * 2);
            double2 wa23 = *(const double2*)(sWaD + c * 128 + o4 * 2 + 4);
            double2 wb01 = *(const double2*)(sWbD + c * 128 + o4 * 2);
            double2 wb23 = *(const double2*)(sWbD + c * 128 + o4 * 2 + 4);
            fma2(aa[0], xv, dal(wa01.x)); fma2(aa[1], xv, dal(wa01.y));
            fma2(aa[2], xv, dal(wa23.x)); fma2(aa[3], xv, dal(wa23.y));
            fma2(ab[0], hv, dal(wb01.x)); fma2(ab[1], hv, dal(wb01.y));
            fma2(ab[2], hv, dal(wb23.x)); fma2(ab[3], hv, dal(wb23.y));
        }

        float2 res[4];
        #pragma unroll
        for (int k = 0; k < 4; ++k) {
            const int o = o4 + k;
            float2 A  = unpk(aa[k]);
            float2 Bv = unpk(ab[k]);
            float2 yv = *(const float2*)(syP + o * 16 + wq);
            const float ba_ = sba[o], bb_ = sbb[o];
            res[k].x = fmaxf(A.x + ba_ + (Bv.x + bb_) * yv.x, 0.f);
            res[k].y = fmaxf(A.y + ba_ + (Bv.y + bb_) * yv.y, 0.f);
        }
        __syncthreads();
        #pragma unroll
        for (int k = 0; k < 4; ++k) {
            const int o = o4 + k;
            *(float2*)(sh + o * 16 + wq) = res[k];
            *(float2*)(hb + o * HWX + r * 128 + wq) = res[k];
        }
    }
}

// ===========================================================================
// Kernel 2: batched 128x128 transpose of last two dims.
// blockIdx.z: [0,512)=y->yT, [512,1024)=hs->hsT, [1024,1536)=hn->hnT
// ===========================================================================
__global__ void __launch_bounds__(256, 1) transpose3_kernel(const float* __restrict__ ysrc)
{
    __shared__ float tile[32][33];
    const int mode = blockIdx.z >> 9;
    const int n    = blockIdx.z & 511;
    const float* src = (mode == 0 ? ysrc : (mode == 1 ? g_hs : g_hn)) + n * HWX;
    float*       dst = (mode == 0 ? g_yT : (mode == 1 ? g_hsT : g_hnT)) + n * HWX;
    const int r0 = blockIdx.y * 32, c0 = blockIdx.x * 32;
    const int tx = threadIdx.x & 31, ty = (threadIdx.x >> 5) * 4;
    #pragma unroll
    for (int k = 0; k < 4; ++k) tile[ty + k][tx] = src[(r0 + ty + k) * 128 + c0 + tx];
    __syncthreads();
    #pragma unroll
    for (int k = 0; k < 4; ++k) dst[(c0 + ty + k) * 128 + r0 + tx] = tile[tx][ty + k];
}

// ===========================================================================
// Kernel 3: column scans, all 4 directions in one launch.
// grid (4 H-chunks [cluster 4], 8 batch, 4 dirs), 128 threads.
// Thread tile: 4 o x 4 h (two f32x2 pairs). Weights PRE-DUPLICATED [c][o*2].
// Base column double-buffered via cp.async; y register double-buffered.
// One gated boundary row exchanged per step via DSMEM + cluster barrier.
// smem (floats): WtD 0 (8192), WaD 8192 (8192), WbD 16384 (8192),
//                bs 24576 (2x2048), cp 28672 (2048), sg 30720 (2048),
//                halo 32768 (2x64), bt 32896, ba 32960, bb 33024
//                -> 33088 fl = 132352 B
// ===========================================================================
__global__ void __launch_bounds__(128, 1) __cluster_dims__(4, 1, 1)
col_scan_kernel(const float* __restrict__ Wc, const float* __restrict__ bc,
                const float* __restrict__ gms)
{
    float* sWtD = smdyn;
    float* sWaD = smdyn + 8192;
    float* sWbD = smdyn + 16384;
    float* bsB  = smdyn + 24576;
    float* cp   = smdyn + 28672;
    float* sg   = smdyn + 30720;
    float* halo = smdyn + 32768;
    float* sbt  = smdyn + 32896;
    float* sba  = smdyn + 32960;
    float* sbb  = smdyn + 33024;

    const int dir = blockIdx.z;     // 0 hse, 1 hsw, 2 hne, 3 hnw
    const int b   = blockIdx.y;
    const int cx  = blockIdx.x;     // cluster rank
    const int r0  = cx * 32;
    const int t   = threadIdx.x;

    int kt;
    if (dir == 0) kt = 2; else if (dir == 1) kt = 5; else if (dir == 2) kt = 10; else kt = 13;
    const int  wdir = (dir & 1) ? -1 : 1;
    const bool shup = (dir >= 2);
    const float gamma = gms[dir];

    for (int idx = t; idx < 4096; idx += 128) {
        int o = idx >> 6, c = idx & 63;
        float wt = Wc[kt * 4096 + idx];
        float wa = Wc[(kt + 1) * 4096 + idx];
        float wb = Wc[(kt + 2) * 4096 + idx];
        sWtD[c * 128 + o * 2] = wt; sWtD[c * 128 + o * 2 + 1] = wt;
        sWaD[c * 128 + o * 2] = wa; sWaD[c * 128 + o * 2 + 1] = wa;
        sWbD[c * 128 + o * 2] = wb; sWbD[c * 128 + o * 2 + 1] = wb;
    }
    if (t < 64) {
        sbt[t] = bc[kt * 64 + t];
        sba[t] = bc[(kt + 1) * 64 + t];
        sbb[t] = bc[(kt + 2) * 64 + t];
    }

    const float* baseb = ((dir < 2) ? g_hsT : g_hnT) + b * CHWX + r0;  // [c][w][h]
    const float* yTb   = g_yT + b * CHWX + r0;
    float*       outb  = g_col[dir] + b * CHWX + r0;

    // init column j0: 16 floats per thread
    {
        const int j0 = (wdir > 0) ? 0 : 127;
        const int c  = t >> 1;
        const int h0 = (t & 1) * 16;
        #pragma unroll
        for (int kk = 0; kk < 4; ++kk) {
            float4 v = relu4(*(const float4*)(baseb + c * HWX + j0 * 128 + h0 + kk * 4));
            *(float4*)(cp + c * 32 + h0 + kk * 4) = v;
            *(float4*)(outb + c * HWX + j0 * 128 + h0 + kk * 4) = v;
        }
    }
    // prefetch base column for step 1 into parity-1 buffer
    {
        const int j1 = (wdir > 0) ? 1 : 126;
        float* nb = bsB + 2048;
        #pragma unroll
        for (int k = 0; k < 4; ++k) {
            int q = t + 128 * k;
            int c = q >> 3, h = (q & 7) * 4;
            cpasync16(nb + c * 32 + h, baseb + c * HWX + j1 * 128 + h);
        }
        cpcommit();
    }

    const int o4 = (t >> 3) * 4;       // 4 out-channels
    const int hq = (t & 7) * 4;        // 4 local h rows

    // y register prefetch: ycur = y(jj=1)'s gate column (yj = init column j0)
    float4 ycur[4];
    {
        const int yj0 = (wdir > 0) ? 0 : 127;
        #pragma unroll
        for (int k = 0; k < 4; ++k)
            ycur[k] = *(const float4*)(yTb + (o4 + k) * HWX + yj0 * 128 + hq);
    }

    for (int jj = 1; jj < 128; ++jj) {
        const int p = jj & 1;
        const float* bsP = bsB + p * 2048;
        const int j  = (wdir > 0) ? jj : 127 - jj;

        cpwait0();
        __syncthreads();

        if (jj < 127) {
            const int j2 = (wdir > 0) ? jj + 1 : 126 - jj;
            float* nb = bsB + (1 - p) * 2048;
            #pragma unroll
            for (int k = 0; k < 4; ++k) {
                int q = t + 128 * k;
                int c = q >> 3, h = (q & 7) * 4;
                cpasync16(nb + c * 32 + h, baseb + c * HWX + j2 * 128 + h);
            }
            cpcommit();
        }

        // prefetch next step's gate column: yj(jj+1) == current j
        float4 ynxt[4];
        if (jj < 127) {
            #pragma unroll
            for (int k = 0; k < 4; ++k)
                ynxt[k] = *(const float4*)(yTb + (o4 + k) * HWX + j * 128 + hq);
        }

        ull aT[4][2], aA[4][2], aB[4][2];
        #pragma unroll
        for (int k = 0; k < 4; ++k) {
            aT[k][0] = aT[k][1] = 0ULL;
            aA[k][0] = aA[k][1] = 0ULL;
            aB[k][0] = aB[k][1] = 0ULL;
        }

        #pragma unroll 8
        for (int c = 0; c < 64; ++c) {
            double2 bv = *(const double2*)(bsP + c * 32 + hq);
            double2 pv = *(const double2*)(cp  + c * 32 + hq);
            ull b0 = dal(bv.x), b1 = dal(bv.y);
            ull p0 = dal(pv.x), p1 = dal(pv.y);
            double2 wt01 = *(const double2*)(sWtD + c * 128 + o4 * 2);
            double2 wt23 = *(const double2*)(sWtD + c * 128 + o4 * 2 + 4);
            double2 wa01 = *(const double2*)(sWaD + c * 128 + o4 * 2);
            double2 wa23 = *(const double2*)(sWaD + c * 128 + o4 * 2 + 4);
            double2 wb01 = *(const double2*)(sWbD + c * 128 + o4 * 2);
            double2 wb23 = *(const double2*)(sWbD + c * 128 + o4 * 2 + 4);
            ull w;
            w = dal(wt01.x); fma2(aT[0][0], p0, w); fma2(aT[0][1], p1, w);
            w = dal(wt01.y); fma2(aT[1][0], p0, w); fma2(aT[1][1], p1, w);
            w = dal(wt23.x); fma2(aT[2][0], p0, w); fma2(aT[2][1], p1, w);
            w = dal(wt23.y); fma2(aT[3][0], p0, w); fma2(aT[3][1], p1, w);
            w = dal(wa01.x); fma2(aA[0][0], b0, w); fma2(aA[0][1], b1, w);
            w = dal(wa01.y); fma2(aA[1][0], b0, w); fma2(aA[1][1], b1, w);
            w = dal(wa23.x); fma2(aA[2][0], b0, w); fma2(aA[2][1], b1, w);
            w = dal(wa23.y); fma2(aA[3][0], b0, w); fma2(aA[3][1], b1, w);
            w = dal(wb01.x); fma2(aB[0][0], p0, w); fma2(aB[0][1], p1, w);
            w = dal(wb01.y); fma2(aB[1][0], p0, w); fma2(aB[1][1], p1, w);
            w = dal(wb23.x); fma2(aB[2][0], p0, w); fma2(aB[2][1], p1, w);
            w = dal(wb23.y); fma2(aB[3][0], p0, w); fma2(aB[3][1], p1, w);
        }

        // gating (scalar epilogue)
        float g[4][4];
        #pragma unroll
        for (int k = 0; k < 4; ++k) {
            float2 t0 = unpk(aT[k][0]), t1 = unpk(aT[k][1]);
            const float bt_ = sbt[o4 + k];
            g[k][0] = (t0.x + bt_) * ycur[k].x;
            g[k][1] = (t0.y + bt_) * ycur[k].y;
            g[k][2] = (t1.x + bt_) * ycur[k].z;
            g[k][3] = (t1.y + bt_) * ycur[k].w;
            *(float4*)(sg + (o4 + k) * 32 + hq) =
                make_float4(g[k][0], g[k][1], g[k][2], g[k][3]);
        }

        // export boundary gated row to H-neighbor's halo (parity double-buffer)
        const int par = p * 64;
        if (!shup) {             // shift_down: my last local row -> cx+1
            if (hq == 28 && cx < 3) {
                #pragma unroll
                for (int k = 0; k < 4; ++k)
                    dsmem_store(halo + par + o4 + k, cx + 1, g[k][3]);
            }
        } else {                 // shift_up: my first local row -> cx-1
            if (hq == 0 && cx > 0) {
                #pragma unroll
                for (int k = 0; k < 4; ++k)
                    dsmem_store(halo + par + o4 + k, cx - 1, g[k][0]);
            }
        }
        asm volatile("barrier.cluster.arrive.aligned;" ::: "memory");
        asm volatile("barrier.cluster.wait.aligned;"   ::: "memory");

        #pragma unroll
        for (int k = 0; k < 4; ++k) {
            const int o = o4 + k;
            float s0, s1, s2, s3;
            if (!shup) {         // shifted[h] = gated[h-1], 0 at global h=0
                float m;
                if (hq > 0)      m = sg[o * 32 + hq - 1];
                else if (cx > 0) m = halo[par + o];
                else             m = 0.f;
                s0 = m; s1 = g[k][0]; s2 = g[k][1]; s3 = g[k][2];
            } else {             // shifted[h] = gated[h+1], 0 at global h=127
                float q_;
                if (hq < 28)     q_ = sg[o * 32 + hq + 4];
                else if (cx < 3) q_ = halo[par + o];
                else             q_ = 0.f;
                s0 = g[k][1]; s1 = g[k][2]; s2 = g[k][3]; s3 = q_;
            }
            float2 A0 = unpk(aA[k][0]), A1 = unpk(aA[k][1]);
            float2 B0 = unpk(aB[k][0]), B1 = unpk(aB[k][1]);
            const float ba_ = sba[o], bb_ = sbb[o];
            float4 cres;
            cres.x = fmaxf(A0.x + ba_ + (B0.x + bb_) * ycur[k].x + gamma * s0, 0.f);
            cres.y = fmaxf(A0.y + ba_ + (B0.y + bb_) * ycur[k].y + gamma * s1, 0.f);
            cres.z = fmaxf(A1.x + ba_ + (B1.x + bb_) * ycur[k].z + gamma * s2, 0.f);
            cres.w = fmaxf(A1.y + ba_ + (B1.y + bb_) * ycur[k].w + gamma * s3, 0.f);
            *(float4*)(cp + o * 32 + hq) = cres;
            *(float4*)(outb + o * HWX + j * 128 + hq) = cres;
        }

        #pragma unroll
        for (int k = 0; k < 4; ++k) ycur[k] = ynxt[k];
    }
}

// ===========================================================================
// Kernel 4: sum four direction buffers ([b][c][w][h]) and transpose to d_out.
// ===========================================================================
__global__ void __launch_bounds__(256, 1) sum_transpose_kernel(float* __restrict__ out)
{
    __shared__ float tile[32][33];
    const int n  = blockIdx.z;                 // b*64 + c
    const int w0 = blockIdx.y * 32, h0 = blockIdx.x * 32;
    const int tx = threadIdx.x & 31, ty = (threadIdx.x >> 5) * 4;
    const float* s0 = g_col[0] + n * HWX;
    const float* s1 = g_col[1] + n * HWX;
    const float* s2 = g_col[2] + n * HWX;
    const float* s3 = g_col[3] + n * HWX;
    #pragma unroll
    for (int k = 0; k < 4; ++k) {
        int idx = (w0 + ty + k) * 128 + h0 + tx;
        tile[ty + k][tx] = s0[idx] + s1[idx] + s2[idx] + s3[idx];
    }
    __syncthreads();
    float* d = out + n * HWX;
    #pragma unroll
    for (int k = 0; k < 4; ++k)
        d[(h0 + ty + k) * 128 + w0 + tx] = tile[tx][ty + k];
}

// ===========================================================================
extern "C" void kernel_launch(void* const* d_in, const int* in_sizes, int n_in,
                              void* d_out, int out_size)
{
    const float* x  = (const float*)d_in[0];
    const float* y  = (const float*)d_in[1];
    const float* Wc = (const float*)d_in[2];
    const float* bc = (const float*)d_in[3];
    const float* gm = (const float*)d_in[4];
    float* out = (float*)d_out;

    const int ROWSMEM = 21632 * 4;  // 86528 B
    const int COLSMEM = 33088 * 4;  // 132352 B
    cudaFuncSetAttribute(row_scan_kernel,
                         cudaFuncAttributeMaxDynamicSharedMemorySize, ROWSMEM);
    cudaFuncSetAttribute(col_scan_kernel,
                         cudaFuncAttributeMaxDynamicSharedMemorySize, COLSMEM);

    row_scan_kernel<<<dim3(8, 8, 2), 128, ROWSMEM>>>(x, y, Wc, bc);
    transpose3_kernel<<<dim3(4, 4, 1536), 256>>>(y);
    col_scan_kernel<<<dim3(4, 8, 4), 128, COLSMEM>>>(Wc, bc, gm);
    sum_transpose_kernel<<<dim3(4, 4, 512), 256>>>(out);

    (void)in_sizes; (void)n_in; (void)out_size;
}